// round 1
// baseline (speedup 1.0000x reference)
#include <cuda_runtime.h>
#include <math.h>

// ---------------- problem constants ----------------
#define TT    2080          // total tokens = 16 + 2048 + 16
#define DM    512
#define NH    8
#define DH    64
#define DI    2048
#define NLAY  4
#define NMTOK 16
#define QL    2048

#define HTT   ((size_t)NH * TT * TT)

// ---------------- scratch (static device globals; no allocation) ----------------
__device__ float g_w[TT * DM];
__device__ float g_pos[TT * DM];
__device__ float g_heads[TT * 3 * DM];
__device__ float g_r[TT * DM];
__device__ float g_AC[(size_t)NH * TT * TT];   // scores -> probs (in place)
__device__ float g_BD[(size_t)NH * TT * TT];   // raw BD before rel_shift
__device__ float g_av[TT * DM];
__device__ float g_tmp[TT * DM];
__device__ float g_ff1[TT * DI];

// ---------------- prep kernels ----------------
__global__ void build_w_kernel(const float* __restrict__ word_emb,
                               const float* __restrict__ mem) {
    int idx = blockIdx.x * blockDim.x + threadIdx.x;
    if (idx >= TT * DM) return;
    int row = idx / DM, c = idx % DM;
    float v;
    if (row < NMTOK)            v = mem[row * DM + c];
    else if (row < NMTOK + QL)  v = word_emb[(row - NMTOK) * DM + c];
    else                        v = mem[(row - NMTOK - QL) * DM + c];
    g_w[idx] = v;
}

__global__ void build_pos_kernel() {
    int idx = blockIdx.x * blockDim.x + threadIdx.x;
    if (idx >= TT * DM) return;
    int row = idx / DM, c = idx % DM;
    int f = (c < DM / 2) ? c : (c - DM / 2);
    // inv_freq = 10000^{-(2f)/512}; compute in double so fp32 rounding matches ref
    double invf = exp(-((double)(2 * f) / (double)DM) * log(10000.0));
    double val = (double)(TT - 1 - row) * invf;
    g_pos[idx] = (float)((c < DM / 2) ? sin(val) : cos(val));
}

// ---------------- generic tiled SGEMM (NN), optional bias/relu, batched ----------------
#define GBM 64
#define GBN 64
#define GBK 16
__global__ void sgemm_nn(const float* __restrict__ A, int lda, size_t aBS,
                         const float* __restrict__ B, int ldb, size_t bBS,
                         float* __restrict__ C, int ldc, size_t cBS,
                         const float* __restrict__ bias,
                         int M, int N, int K, int doRelu) {
    __shared__ float As[GBK][GBM + 4];
    __shared__ float Bs[GBK][GBN + 4];
    int bz = blockIdx.z;
    A += (size_t)bz * aBS;
    B += (size_t)bz * bBS;
    C += (size_t)bz * cBS;
    int bm = blockIdx.y * GBM, bn = blockIdx.x * GBN;
    int tid = threadIdx.x;
    int tr = tid >> 4, tc = tid & 15;
    float acc[4][4] = {};
    for (int k0 = 0; k0 < K; k0 += GBK) {
        #pragma unroll
        for (int i = tid; i < GBM * GBK; i += 256) {
            int m = i >> 4, k = i & 15;
            float v = 0.f;
            if (bm + m < M) v = A[(size_t)(bm + m) * lda + k0 + k];
            As[k][m] = v;
        }
        #pragma unroll
        for (int i = tid; i < GBK * GBN; i += 256) {
            int k = i >> 6, n = i & 63;
            float v = 0.f;
            if (bn + n < N) v = B[(size_t)(k0 + k) * ldb + bn + n];
            Bs[k][n] = v;
        }
        __syncthreads();
        #pragma unroll
        for (int k = 0; k < GBK; k++) {
            float a[4], bb[4];
            #pragma unroll
            for (int u = 0; u < 4; u++) a[u] = As[k][tr * 4 + u];
            #pragma unroll
            for (int u = 0; u < 4; u++) bb[u] = Bs[k][tc * 4 + u];
            #pragma unroll
            for (int x = 0; x < 4; x++)
                #pragma unroll
                for (int y = 0; y < 4; y++)
                    acc[x][y] += a[x] * bb[y];
        }
        __syncthreads();
    }
    #pragma unroll
    for (int x = 0; x < 4; x++) {
        int m = bm + tr * 4 + x;
        if (m >= M) continue;
        #pragma unroll
        for (int y = 0; y < 4; y++) {
            int n = bn + tc * 4 + y;
            if (n >= N) continue;
            float v = acc[x][y];
            if (bias) v += bias[n];
            if (doRelu) v = fmaxf(v, 0.f);
            C[(size_t)m * ldc + n] = v;
        }
    }
}

// ---------------- relative-attention score GEMM: C[h,i,j] = (Q_i + qbias_h) . K_j ----------------
__global__ void score_nt(const float* __restrict__ Q, int ldq, int qcolBase,
                         const float* __restrict__ Km, int ldk, int kcolBase,
                         const float* __restrict__ qbias,   // [NH*DH]
                         float* __restrict__ Out) {
    int h = blockIdx.z;
    __shared__ float Qs[DH][64 + 4];
    __shared__ float Ks[DH][64 + 4];
    int i0 = blockIdx.y * 64, j0 = blockIdx.x * 64;
    int tid = threadIdx.x, tr = tid >> 4, tc = tid & 15;
    for (int t = tid; t < 64 * DH; t += 256) {
        int m = t >> 6, d = t & 63;
        float v = 0.f;
        int row = i0 + m;
        if (row < TT) v = Q[(size_t)row * ldq + qcolBase + h * DH + d] + qbias[h * DH + d];
        Qs[d][m] = v;
    }
    for (int t = tid; t < 64 * DH; t += 256) {
        int n = t >> 6, d = t & 63;
        float v = 0.f;
        int row = j0 + n;
        if (row < TT) v = Km[(size_t)row * ldk + kcolBase + h * DH + d];
        Ks[d][n] = v;
    }
    __syncthreads();
    float acc[4][4] = {};
    #pragma unroll
    for (int d = 0; d < DH; d++) {
        float a[4], bb[4];
        #pragma unroll
        for (int u = 0; u < 4; u++) a[u] = Qs[d][tr * 4 + u];
        #pragma unroll
        for (int u = 0; u < 4; u++) bb[u] = Ks[d][tc * 4 + u];
        #pragma unroll
        for (int x = 0; x < 4; x++)
            #pragma unroll
            for (int y = 0; y < 4; y++)
                acc[x][y] += a[x] * bb[y];
    }
    float* Ch = Out + (size_t)h * TT * TT;
    #pragma unroll
    for (int x = 0; x < 4; x++) {
        int i = i0 + tr * 4 + x;
        if (i >= TT) continue;
        #pragma unroll
        for (int y = 0; y < 4; y++) {
            int j = j0 + tc * 4 + y;
            if (j >= TT) continue;
            Ch[(size_t)i * TT + j] = acc[x][y];
        }
    }
}

// ---------------- combine: rel_shift(BD) + AC, scale, mask ----------------
__global__ void combine_kernel(float* __restrict__ AC, const float* __restrict__ BD) {
    size_t idx = (size_t)blockIdx.x * blockDim.x + threadIdx.x;
    if (idx >= HTT) return;
    int j = (int)(idx % TT);
    size_t t = idx / TT;
    int i = (int)(t % TT);
    int h = (int)(t / TT);
    const float* BDh = BD + (size_t)h * TT * TT;
    float bd;
    if (j <= i)            bd = BDh[(size_t)i * TT + (TT - 1 - i + j)];
    else if (j == i + 1)   bd = 0.f;                                   // rel_shift pad column
    else                   bd = BDh[(size_t)(i + 1) * TT + (j - i - 2)]; // rel_shift wraparound
    bool masked = (j > i) && !((i < NMTOK && j < NMTOK) ||
                               (i >= TT - NMTOK && j >= TT - NMTOK));
    AC[idx] = masked ? -1e30f : (AC[idx] + bd) * 0.125f;  // 1/sqrt(64)
}

// ---------------- row softmax over j (in place) ----------------
__global__ void softmax_kernel(float* __restrict__ P) {
    size_t row = blockIdx.x;            // NH*TT rows
    float* x = P + row * TT;
    __shared__ float red[256];
    int tid = threadIdx.x;
    float m = -1e38f;
    for (int j = tid; j < TT; j += 256) m = fmaxf(m, x[j]);
    red[tid] = m; __syncthreads();
    for (int s = 128; s > 0; s >>= 1) {
        if (tid < s) red[tid] = fmaxf(red[tid], red[tid + s]);
        __syncthreads();
    }
    m = red[0]; __syncthreads();
    float sum = 0.f;
    for (int j = tid; j < TT; j += 256) {
        float e = expf(x[j] - m);
        x[j] = e;
        sum += e;
    }
    red[tid] = sum; __syncthreads();
    for (int s = 128; s > 0; s >>= 1) {
        if (tid < s) red[tid] += red[tid + s];
        __syncthreads();
    }
    float inv = 1.f / red[0];
    for (int j = tid; j < TT; j += 256) x[j] *= inv;
}

// ---------------- residual add + layernorm (in place on g_w) ----------------
__global__ void add_ln_kernel(float* __restrict__ w, const float* __restrict__ delta,
                              const float* __restrict__ gam, const float* __restrict__ bta) {
    int row = blockIdx.x;
    int tid = threadIdx.x;  // 256 threads, 2 elems each (DM=512)
    __shared__ float red[256];
    float x0 = w[row * DM + tid]       + delta[row * DM + tid];
    float x1 = w[row * DM + tid + 256] + delta[row * DM + tid + 256];
    red[tid] = x0 + x1; __syncthreads();
    for (int s = 128; s > 0; s >>= 1) {
        if (tid < s) red[tid] += red[tid + s];
        __syncthreads();
    }
    float mean = red[0] * (1.f / DM);
    __syncthreads();
    float d0 = x0 - mean, d1 = x1 - mean;
    red[tid] = d0 * d0 + d1 * d1; __syncthreads();
    for (int s = 128; s > 0; s >>= 1) {
        if (tid < s) red[tid] += red[tid + s];
        __syncthreads();
    }
    float inv = 1.f / sqrtf(red[0] * (1.f / DM) + 1e-5f);
    w[row * DM + tid]       = d0 * inv * gam[tid]       + bta[tid];
    w[row * DM + tid + 256] = d1 * inv * gam[tid + 256] + bta[tid + 256];
}

__global__ void copy_out_kernel(float* __restrict__ out) {
    int idx = blockIdx.x * blockDim.x + threadIdx.x;
    if (idx < TT * DM) out[idx] = g_w[idx];
}

// ---------------- launcher ----------------
extern "C" void kernel_launch(void* const* d_in, const int* in_sizes, int n_in,
                              void* d_out, int out_size) {
    (void)in_sizes; (void)n_in; (void)out_size;
    const float* word_emb = (const float*)d_in[0];
    const float* mem_tok  = (const float*)d_in[1];
    const float* Wqkv     = (const float*)d_in[2];
    const float* Wr       = (const float*)d_in[3];
    const float* Wo       = (const float*)d_in[4];
    const float* ln1s     = (const float*)d_in[5];
    const float* ln1b     = (const float*)d_in[6];
    const float* W1       = (const float*)d_in[7];
    const float* b1       = (const float*)d_in[8];
    const float* W2       = (const float*)d_in[9];
    const float* b2       = (const float*)d_in[10];
    const float* ln2s     = (const float*)d_in[11];
    const float* ln2b     = (const float*)d_in[12];
    const float* rwb      = (const float*)d_in[13];
    const float* rrb      = (const float*)d_in[14];

    float* g_w_p;    cudaGetSymbolAddress((void**)&g_w_p,    g_w);
    float* g_pos_p;  cudaGetSymbolAddress((void**)&g_pos_p,  g_pos);
    float* g_hd_p;   cudaGetSymbolAddress((void**)&g_hd_p,   g_heads);
    float* g_r_p;    cudaGetSymbolAddress((void**)&g_r_p,    g_r);
    float* g_AC_p;   cudaGetSymbolAddress((void**)&g_AC_p,   g_AC);
    float* g_BD_p;   cudaGetSymbolAddress((void**)&g_BD_p,   g_BD);
    float* g_av_p;   cudaGetSymbolAddress((void**)&g_av_p,   g_av);
    float* g_tmp_p;  cudaGetSymbolAddress((void**)&g_tmp_p,  g_tmp);
    float* g_ff1_p;  cudaGetSymbolAddress((void**)&g_ff1_p,  g_ff1);

    const int TD = TT * DM;
    build_w_kernel<<<(TD + 255) / 256, 256>>>(word_emb, mem_tok);
    build_pos_kernel<<<(TD + 255) / 256, 256>>>();

    const int TI64 = (TT + 63) / 64;   // 33

    for (int l = 0; l < NLAY; l++) {
        // QKV projection: heads[T,1536] = w @ Wqkv[l]
        sgemm_nn<<<dim3(3 * DM / 64, TI64, 1), 256>>>(
            g_w_p, DM, 0, Wqkv + (size_t)l * DM * 3 * DM, 3 * DM, 0,
            g_hd_p, 3 * DM, 0, nullptr, TT, 3 * DM, DM, 0);
        // R projection: r[T,512] = pos_emb @ Wr[l]
        sgemm_nn<<<dim3(DM / 64, TI64, 1), 256>>>(
            g_pos_p, DM, 0, Wr + (size_t)l * DM * DM, DM, 0,
            g_r_p, DM, 0, nullptr, TT, DM, DM, 0);
        // AC[h,i,j] = (q_i + r_w_bias_h) . k_j
        score_nt<<<dim3(TI64, TI64, NH), 256>>>(
            g_hd_p, 3 * DM, 0, g_hd_p, 3 * DM, DM, rwb, g_AC_p);
        // BDraw[h,i,j] = (q_i + r_r_bias_h) . r_j
        score_nt<<<dim3(TI64, TI64, NH), 256>>>(
            g_hd_p, 3 * DM, 0, g_r_p, DM, 0, rrb, g_BD_p);
        // rel_shift + add + scale + mask
        combine_kernel<<<(unsigned)((HTT + 255) / 256), 256>>>(g_AC_p, g_BD_p);
        // softmax over j
        softmax_kernel<<<NH * TT, 256>>>(g_AC_p);
        // attn_vec: av[:, h*64:(h+1)*64] = prob_h @ V_h   (batched over heads)
        sgemm_nn<<<dim3(1, TI64, NH), 256>>>(
            g_AC_p, TT, (size_t)TT * TT,
            g_hd_p + 2 * DM, 3 * DM, DH,
            g_av_p, DM, DH, nullptr, TT, DH, TT, 0);
        // output projection
        sgemm_nn<<<dim3(DM / 64, TI64, 1), 256>>>(
            g_av_p, DM, 0, Wo + (size_t)l * DM * DM, DM, 0,
            g_tmp_p, DM, 0, nullptr, TT, DM, DM, 0);
        add_ln_kernel<<<TT, 256>>>(g_w_p, g_tmp_p, ln1s + l * DM, ln1b + l * DM);
        // FFN
        sgemm_nn<<<dim3(DI / 64, TI64, 1), 256>>>(
            g_w_p, DM, 0, W1 + (size_t)l * DM * DI, DI, 0,
            g_ff1_p, DI, 0, b1 + (size_t)l * DI, TT, DI, DM, 1);
        sgemm_nn<<<dim3(DM / 64, TI64, 1), 256>>>(
            g_ff1_p, DI, 0, W2 + (size_t)l * DI * DM, DM, 0,
            g_tmp_p, DM, 0, b2 + (size_t)l * DM, TT, DM, DI, 0);
        add_ln_kernel<<<TT, 256>>>(g_w_p, g_tmp_p, ln2s + l * DM, ln2b + l * DM);
    }

    copy_out_kernel<<<(TD + 255) / 256, 256>>>((float*)d_out);
}

// round 2
// speedup vs baseline: 2.3123x; 2.3123x over previous
#include <cuda_runtime.h>
#include <math.h>
#include <stdint.h>

// ---------------- problem constants ----------------
#define TT    2080
#define DM    512
#define NH    8
#define DH    64
#define DI    2048
#define NLAY  4
#define NMTOK 16
#define QL    2048
#define HTT   ((size_t)NH * TT * TT)

// ---------------- scratch ----------------
__device__ float g_w[TT * DM];
__device__ float g_pos[TT * DM];
__device__ float g_heads[TT * 3 * DM];
__device__ float g_r[TT * DM];
__device__ float g_AC[(size_t)NH * TT * TT];
__device__ float g_BD[(size_t)NH * TT * TT];
__device__ float g_av[TT * DM];
__device__ float g_tmp[TT * DM];
__device__ float g_ff1[TT * DI];

// ---------------- prep kernels ----------------
__global__ void build_w_kernel(const float* __restrict__ word_emb,
                               const float* __restrict__ mem) {
    int idx = blockIdx.x * blockDim.x + threadIdx.x;
    if (idx >= TT * DM) return;
    int row = idx / DM, c = idx % DM;
    float v;
    if (row < NMTOK)            v = mem[row * DM + c];
    else if (row < NMTOK + QL)  v = word_emb[(row - NMTOK) * DM + c];
    else                        v = mem[(row - NMTOK - QL) * DM + c];
    g_w[idx] = v;
}

__global__ void build_pos_kernel() {
    int idx = blockIdx.x * blockDim.x + threadIdx.x;
    if (idx >= TT * DM) return;
    int row = idx / DM, c = idx % DM;
    int f = (c < DM / 2) ? c : (c - DM / 2);
    double invf = exp(-((double)(2 * f) / (double)DM) * log(10000.0));
    double val = (double)(TT - 1 - row) * invf;
    g_pos[idx] = (float)((c < DM / 2) ? sin(val) : cos(val));
}

// ---------------- 3xTF32 MMA GEMM ----------------
// C[M,N] = A[M,K] * op(B),  op(B)=B[K,N] (NN) or B[N,K]^T (NT)
// Block tile 128x64, BK=32. 8 warps: 4 along M (32 rows) x 2 along N (32 cols).
// Per warp: 2 m-atoms (m16) x 4 n-atoms (n8), mma.m16n8k8.tf32, 3x split.

__device__ __forceinline__ void split_tf32(float x, uint32_t& hi, uint32_t& lo) {
    uint32_t h;
    asm("cvt.rna.tf32.f32 %0, %1;" : "=r"(h) : "f"(x));
    float r = x - __uint_as_float(h);
    uint32_t l;
    asm("cvt.rna.tf32.f32 %0, %1;" : "=r"(l) : "f"(r));
    hi = h; lo = l;
}

__device__ __forceinline__ void mma8(float (&c)[4], const uint32_t (&a)[4],
                                     const uint32_t (&b)[2]) {
    asm volatile(
        "mma.sync.aligned.m16n8k8.row.col.f32.tf32.tf32.f32 "
        "{%0,%1,%2,%3}, {%4,%5,%6,%7}, {%8,%9}, {%0,%1,%2,%3};"
        : "+f"(c[0]), "+f"(c[1]), "+f"(c[2]), "+f"(c[3])
        : "r"(a[0]), "r"(a[1]), "r"(a[2]), "r"(a[3]), "r"(b[0]), "r"(b[1]));
}

#define LDA_S 36   // As row stride (m-major [128][36])
#define LDB_NN 72  // Bs row stride for NN ([32][72], k-major)
#define LDB_NT 36  // Bs row stride for NT ([64][36], n-major)

template<bool TRANSB>
__global__ __launch_bounds__(256)
void mma_gemm(const float* __restrict__ A, int lda, size_t aBS,
              const float* __restrict__ abias, int abiasBS,
              const float* __restrict__ B, int ldb, size_t bBS,
              float* __restrict__ C, int ldc, size_t cBS,
              const float* __restrict__ cbias, int doRelu,
              int M, int N, int K) {
    __shared__ float As[128 * LDA_S];
    __shared__ float Bs[64 * 36];   // 2304 floats; NN views it as [32][72]

    const int bm = blockIdx.y * 128, bn = blockIdx.x * 64, bz = blockIdx.z;
    A += (size_t)bz * aBS;
    B += (size_t)bz * bBS;
    C += (size_t)bz * cBS;
    const float* ab = abias ? abias + (size_t)bz * abiasBS : nullptr;

    const int tid = threadIdx.x;
    const int lane = tid & 31, warp = tid >> 5;
    const int wm = warp & 3, wn = warp >> 2;      // 4 x 2 warps
    const int g4 = lane >> 2, l4 = lane & 3;

    float acc[2][4][4] = {};
    float4 pa[4], pb[2];

    // ---- global load helpers (into registers) ----
    auto loadA = [&](int k0) {
        const int r = tid >> 3, k4 = (tid & 7) * 4;
        #pragma unroll
        for (int p = 0; p < 4; p++) {
            int row = bm + p * 32 + r;
            float4 v = make_float4(0.f, 0.f, 0.f, 0.f);
            if (row < M) v = *reinterpret_cast<const float4*>(A + (size_t)row * lda + k0 + k4);
            if (ab) {
                v.x += ab[k0 + k4 + 0];
                v.y += ab[k0 + k4 + 1];
                v.z += ab[k0 + k4 + 2];
                v.w += ab[k0 + k4 + 3];
            }
            pa[p] = v;
        }
    };
    auto loadB = [&](int k0) {
        if (TRANSB) {
            const int r = tid >> 3, k4 = (tid & 7) * 4;
            #pragma unroll
            for (int p = 0; p < 2; p++) {
                int row = bn + p * 32 + r;   // n dimension
                float4 v = make_float4(0.f, 0.f, 0.f, 0.f);
                if (row < N) v = *reinterpret_cast<const float4*>(B + (size_t)row * ldb + k0 + k4);
                pb[p] = v;
            }
        } else {
            const int r = tid >> 4, n4 = (tid & 15) * 4;
            #pragma unroll
            for (int p = 0; p < 2; p++) {
                int k = k0 + p * 16 + r;
                pb[p] = *reinterpret_cast<const float4*>(B + (size_t)k * ldb + bn + n4);
            }
        }
    };
    auto storeAB = [&]() {
        {
            const int r = tid >> 3, k4 = (tid & 7) * 4;
            #pragma unroll
            for (int p = 0; p < 4; p++)
                *reinterpret_cast<float4*>(&As[(p * 32 + r) * LDA_S + k4]) = pa[p];
        }
        if (TRANSB) {
            const int r = tid >> 3, k4 = (tid & 7) * 4;
            #pragma unroll
            for (int p = 0; p < 2; p++)
                *reinterpret_cast<float4*>(&Bs[(p * 32 + r) * LDB_NT + k4]) = pb[p];
        } else {
            const int r = tid >> 4, n4 = (tid & 15) * 4;
            #pragma unroll
            for (int p = 0; p < 2; p++)
                *reinterpret_cast<float4*>(&Bs[(p * 16 + r) * LDB_NN + n4]) = pb[p];
        }
    };

    loadA(0);
    loadB(0);

    for (int k0 = 0; k0 < K; k0 += 32) {
        storeAB();
        __syncthreads();
        if (k0 + 32 < K) { loadA(k0 + 32); loadB(k0 + 32); }

        #pragma unroll
        for (int ks = 0; ks < 4; ks++) {
            const int kk = ks * 8 + l4;
            uint32_t ah[2][4], al[2][4];
            #pragma unroll
            for (int am = 0; am < 2; am++) {
                int mb = wm * 32 + am * 16 + g4;
                float f0 = As[mb * LDA_S + kk];
                float f1 = As[(mb + 8) * LDA_S + kk];
                float f2 = As[mb * LDA_S + kk + 4];
                float f3 = As[(mb + 8) * LDA_S + kk + 4];
                split_tf32(f0, ah[am][0], al[am][0]);
                split_tf32(f1, ah[am][1], al[am][1]);
                split_tf32(f2, ah[am][2], al[am][2]);
                split_tf32(f3, ah[am][3], al[am][3]);
            }
            uint32_t bh[4][2], bl[4][2];
            #pragma unroll
            for (int an = 0; an < 4; an++) {
                int nb = wn * 32 + an * 8 + g4;
                float f0, f1;
                if (TRANSB) {
                    f0 = Bs[nb * LDB_NT + kk];
                    f1 = Bs[nb * LDB_NT + kk + 4];
                } else {
                    f0 = Bs[kk * LDB_NN + nb];
                    f1 = Bs[(kk + 4) * LDB_NN + nb];
                }
                split_tf32(f0, bh[an][0], bl[an][0]);
                split_tf32(f1, bh[an][1], bl[an][1]);
            }
            #pragma unroll
            for (int am = 0; am < 2; am++)
                #pragma unroll
                for (int an = 0; an < 4; an++) {
                    mma8(acc[am][an], ah[am], bh[an]);
                    mma8(acc[am][an], ah[am], bl[an]);
                    mma8(acc[am][an], al[am], bh[an]);
                }
        }
        __syncthreads();
    }

    // ---- epilogue ----
    #pragma unroll
    for (int am = 0; am < 2; am++) {
        int row0 = bm + wm * 32 + am * 16 + g4;
        #pragma unroll
        for (int an = 0; an < 4; an++) {
            int col0 = bn + wn * 32 + an * 8 + 2 * l4;
            float v0 = acc[am][an][0], v1 = acc[am][an][1];
            float v2 = acc[am][an][2], v3 = acc[am][an][3];
            if (cbias) {
                float b0 = cbias[col0], b1 = cbias[col0 + 1];
                v0 += b0; v1 += b1; v2 += b0; v3 += b1;
            }
            if (doRelu) {
                v0 = fmaxf(v0, 0.f); v1 = fmaxf(v1, 0.f);
                v2 = fmaxf(v2, 0.f); v3 = fmaxf(v3, 0.f);
            }
            if (row0 < M) {
                if (col0 < N)     C[(size_t)row0 * ldc + col0]     = v0;
                if (col0 + 1 < N) C[(size_t)row0 * ldc + col0 + 1] = v1;
            }
            if (row0 + 8 < M) {
                if (col0 < N)     C[(size_t)(row0 + 8) * ldc + col0]     = v2;
                if (col0 + 1 < N) C[(size_t)(row0 + 8) * ldc + col0 + 1] = v3;
            }
        }
    }
}

// ---------------- combine: rel_shift(BD) + AC, scale, mask ----------------
__global__ void combine_kernel(float* __restrict__ AC, const float* __restrict__ BD) {
    size_t idx = (size_t)blockIdx.x * blockDim.x + threadIdx.x;
    if (idx >= HTT) return;
    int j = (int)(idx % TT);
    size_t t = idx / TT;
    int i = (int)(t % TT);
    int h = (int)(t / TT);
    const float* BDh = BD + (size_t)h * TT * TT;
    float bd;
    if (j <= i)            bd = BDh[(size_t)i * TT + (TT - 1 - i + j)];
    else if (j == i + 1)   bd = 0.f;
    else                   bd = BDh[(size_t)(i + 1) * TT + (j - i - 2)];
    bool masked = (j > i) && !((i < NMTOK && j < NMTOK) ||
                               (i >= TT - NMTOK && j >= TT - NMTOK));
    AC[idx] = masked ? -1e30f : (AC[idx] + bd) * 0.125f;
}

// ---------------- row softmax ----------------
__global__ void softmax_kernel(float* __restrict__ P) {
    size_t row = blockIdx.x;
    float* x = P + row * TT;
    __shared__ float red[256];
    int tid = threadIdx.x;
    float m = -1e38f;
    for (int j = tid; j < TT; j += 256) m = fmaxf(m, x[j]);
    red[tid] = m; __syncthreads();
    for (int s = 128; s > 0; s >>= 1) {
        if (tid < s) red[tid] = fmaxf(red[tid], red[tid + s]);
        __syncthreads();
    }
    m = red[0]; __syncthreads();
    float sum = 0.f;
    for (int j = tid; j < TT; j += 256) {
        float e = expf(x[j] - m);
        x[j] = e;
        sum += e;
    }
    red[tid] = sum; __syncthreads();
    for (int s = 128; s > 0; s >>= 1) {
        if (tid < s) red[tid] += red[tid + s];
        __syncthreads();
    }
    float inv = 1.f / red[0];
    for (int j = tid; j < TT; j += 256) x[j] *= inv;
}

// ---------------- residual add + layernorm ----------------
__global__ void add_ln_kernel(float* __restrict__ w, const float* __restrict__ delta,
                              const float* __restrict__ gam, const float* __restrict__ bta) {
    int row = blockIdx.x;
    int tid = threadIdx.x;
    __shared__ float red[256];
    float x0 = w[row * DM + tid]       + delta[row * DM + tid];
    float x1 = w[row * DM + tid + 256] + delta[row * DM + tid + 256];
    red[tid] = x0 + x1; __syncthreads();
    for (int s = 128; s > 0; s >>= 1) {
        if (tid < s) red[tid] += red[tid + s];
        __syncthreads();
    }
    float mean = red[0] * (1.f / DM);
    __syncthreads();
    float d0 = x0 - mean, d1 = x1 - mean;
    red[tid] = d0 * d0 + d1 * d1; __syncthreads();
    for (int s = 128; s > 0; s >>= 1) {
        if (tid < s) red[tid] += red[tid + s];
        __syncthreads();
    }
    float inv = 1.f / sqrtf(red[0] * (1.f / DM) + 1e-5f);
    w[row * DM + tid]       = d0 * inv * gam[tid]       + bta[tid];
    w[row * DM + tid + 256] = d1 * inv * gam[tid + 256] + bta[tid + 256];
}

__global__ void copy_out_kernel(float* __restrict__ out) {
    int idx = blockIdx.x * blockDim.x + threadIdx.x;
    if (idx < TT * DM) out[idx] = g_w[idx];
}

// ---------------- launcher ----------------
extern "C" void kernel_launch(void* const* d_in, const int* in_sizes, int n_in,
                              void* d_out, int out_size) {
    (void)in_sizes; (void)n_in; (void)out_size;
    const float* word_emb = (const float*)d_in[0];
    const float* mem_tok  = (const float*)d_in[1];
    const float* Wqkv     = (const float*)d_in[2];
    const float* Wr       = (const float*)d_in[3];
    const float* Wo       = (const float*)d_in[4];
    const float* ln1s     = (const float*)d_in[5];
    const float* ln1b     = (const float*)d_in[6];
    const float* W1       = (const float*)d_in[7];
    const float* b1       = (const float*)d_in[8];
    const float* W2       = (const float*)d_in[9];
    const float* b2       = (const float*)d_in[10];
    const float* ln2s     = (const float*)d_in[11];
    const float* ln2b     = (const float*)d_in[12];
    const float* rwb      = (const float*)d_in[13];
    const float* rrb      = (const float*)d_in[14];

    float *g_w_p, *g_pos_p, *g_hd_p, *g_r_p, *g_AC_p, *g_BD_p, *g_av_p, *g_tmp_p, *g_ff1_p;
    cudaGetSymbolAddress((void**)&g_w_p,   g_w);
    cudaGetSymbolAddress((void**)&g_pos_p, g_pos);
    cudaGetSymbolAddress((void**)&g_hd_p,  g_heads);
    cudaGetSymbolAddress((void**)&g_r_p,   g_r);
    cudaGetSymbolAddress((void**)&g_AC_p,  g_AC);
    cudaGetSymbolAddress((void**)&g_BD_p,  g_BD);
    cudaGetSymbolAddress((void**)&g_av_p,  g_av);
    cudaGetSymbolAddress((void**)&g_tmp_p, g_tmp);
    cudaGetSymbolAddress((void**)&g_ff1_p, g_ff1);

    const int TD = TT * DM;
    build_w_kernel<<<(TD + 255) / 256, 256>>>(word_emb, mem_tok);
    build_pos_kernel<<<(TD + 255) / 256, 256>>>();

    const int MB = (TT + 127) / 128;   // 17
    const int NB64 = (TT + 63) / 64;   // 33

    for (int l = 0; l < NLAY; l++) {
        // QKV: heads[T,1536] = w @ Wqkv[l]
        mma_gemm<false><<<dim3(3 * DM / 64, MB, 1), 256>>>(
            g_w_p, DM, 0, nullptr, 0,
            Wqkv + (size_t)l * DM * 3 * DM, 3 * DM, 0,
            g_hd_p, 3 * DM, 0, nullptr, 0, TT, 3 * DM, DM);
        // R: r[T,512] = pos @ Wr[l]
        mma_gemm<false><<<dim3(DM / 64, MB, 1), 256>>>(
            g_pos_p, DM, 0, nullptr, 0,
            Wr + (size_t)l * DM * DM, DM, 0,
            g_r_p, DM, 0, nullptr, 0, TT, DM, DM);
        // AC[h,i,j] = (q_i + rwb_h) . k_j     (NT, batched over heads)
        mma_gemm<true><<<dim3(NB64, MB, NH), 256>>>(
            g_hd_p, 3 * DM, DH, rwb, DH,
            g_hd_p + DM, 3 * DM, DH,
            g_AC_p, TT, (size_t)TT * TT, nullptr, 0, TT, TT, DH);
        // BDraw[h,i,j] = (q_i + rrb_h) . r_j
        mma_gemm<true><<<dim3(NB64, MB, NH), 256>>>(
            g_hd_p, 3 * DM, DH, rrb, DH,
            g_r_p, DM, DH,
            g_BD_p, TT, (size_t)TT * TT, nullptr, 0, TT, TT, DH);
        // rel_shift + add + scale + mask
        combine_kernel<<<(unsigned)((HTT + 255) / 256), 256>>>(g_AC_p, g_BD_p);
        softmax_kernel<<<NH * TT, 256>>>(g_AC_p);
        // attn_vec: av[:, h*64:] = prob_h @ V_h
        mma_gemm<false><<<dim3(1, MB, NH), 256>>>(
            g_AC_p, TT, (size_t)TT * TT, nullptr, 0,
            g_hd_p + 2 * DM, 3 * DM, DH,
            g_av_p, DM, DH, nullptr, 0, TT, DH, TT);
        // Wo
        mma_gemm<false><<<dim3(DM / 64, MB, 1), 256>>>(
            g_av_p, DM, 0, nullptr, 0,
            Wo + (size_t)l * DM * DM, DM, 0,
            g_tmp_p, DM, 0, nullptr, 0, TT, DM, DM);
        add_ln_kernel<<<TT, 256>>>(g_w_p, g_tmp_p, ln1s + l * DM, ln1b + l * DM);
        // FFN
        mma_gemm<false><<<dim3(DI / 64, MB, 1), 256>>>(
            g_w_p, DM, 0, nullptr, 0,
            W1 + (size_t)l * DM * DI, DI, 0,
            g_ff1_p, DI, 0, b1 + (size_t)l * DI, 1, TT, DI, DM);
        mma_gemm<false><<<dim3(DM / 64, MB, 1), 256>>>(
            g_ff1_p, DI, 0, nullptr, 0,
            W2 + (size_t)l * DI * DM, DM, 0,
            g_tmp_p, DM, 0, b2 + (size_t)l * DM, 0, TT, DM, DI);
        add_ln_kernel<<<TT, 256>>>(g_w_p, g_tmp_p, ln2s + l * DM, ln2b + l * DM);
    }

    copy_out_kernel<<<(TD + 255) / 256, 256>>>((float*)d_out);
}

// round 3
// speedup vs baseline: 3.1827x; 1.3764x over previous
#include <cuda_runtime.h>
#include <math.h>
#include <stdint.h>

// ---------------- problem constants ----------------
#define TT    2080
#define DM    512
#define NH    8
#define DH    64
#define DI    2048
#define NLAY  4
#define NMTOK 16
#define QL    2048
#define HTT   ((size_t)NH * TT * TT)

// ---------------- scratch ----------------
__device__ float g_w[TT * DM];
__device__ float g_pos[TT * DM];
__device__ float g_heads[TT * 3 * DM];
__device__ float g_r[TT * DM];
__device__ float g_AC[(size_t)NH * TT * TT];
__device__ float g_BD[(size_t)NH * TT * TT];
__device__ float g_av[TT * DM];
__device__ float g_tmp[TT * DM];
__device__ float g_ff1[TT * DI];

// ---------------- prep kernels ----------------
__global__ void build_w_kernel(const float* __restrict__ word_emb,
                               const float* __restrict__ mem) {
    int idx = blockIdx.x * blockDim.x + threadIdx.x;
    if (idx >= TT * DM) return;
    int row = idx / DM, c = idx % DM;
    float v;
    if (row < NMTOK)            v = mem[row * DM + c];
    else if (row < NMTOK + QL)  v = word_emb[(row - NMTOK) * DM + c];
    else                        v = mem[(row - NMTOK - QL) * DM + c];
    g_w[idx] = v;
}

__global__ void build_pos_kernel() {
    int idx = blockIdx.x * blockDim.x + threadIdx.x;
    if (idx >= TT * DM) return;
    int row = idx / DM, c = idx % DM;
    int f = (c < DM / 2) ? c : (c - DM / 2);
    double invf = exp(-((double)(2 * f) / (double)DM) * log(10000.0));
    double val = (double)(TT - 1 - row) * invf;
    g_pos[idx] = (float)((c < DM / 2) ? sin(val) : cos(val));
}

// ---------------- 3xTF32 MMA GEMM ----------------
__device__ __forceinline__ void split_tf32(float x, uint32_t& hi, uint32_t& lo) {
    uint32_t h;
    asm("cvt.rna.tf32.f32 %0, %1;" : "=r"(h) : "f"(x));
    float r = x - __uint_as_float(h);
    uint32_t l;
    asm("cvt.rna.tf32.f32 %0, %1;" : "=r"(l) : "f"(r));
    hi = h; lo = l;
}

__device__ __forceinline__ void mma8(float (&c)[4], const uint32_t (&a)[4],
                                     const uint32_t (&b)[2]) {
    asm volatile(
        "mma.sync.aligned.m16n8k8.row.col.f32.tf32.tf32.f32 "
        "{%0,%1,%2,%3}, {%4,%5,%6,%7}, {%8,%9}, {%0,%1,%2,%3};"
        : "+f"(c[0]), "+f"(c[1]), "+f"(c[2]), "+f"(c[3])
        : "r"(a[0]), "r"(a[1]), "r"(a[2]), "r"(a[3]), "r"(b[0]), "r"(b[1]));
}

#define LDA_S 36
#define LDB_NN 72
#define LDB_NT 36

// skipMode: 0=none, 1=AC (skip tiles fully above causal diag), 2=BD-raw (keep
// anti-diagonal band + col-0 mem strips). kLimitByRow: K_eff = min(K, bm+128).
template<bool TRANSB>
__global__ __launch_bounds__(256, 2)
void mma_gemm(const float* __restrict__ A, int lda, size_t aBS,
              const float* __restrict__ abias, int abiasBS,
              const float* __restrict__ B, int ldb, size_t bBS,
              float* __restrict__ C, int ldc, size_t cBS,
              const float* __restrict__ cbias, int doRelu,
              int M, int N, int K, int skipMode, int kLimitByRow) {
    __shared__ float As[128 * LDA_S];
    __shared__ float Bs[64 * 36];

    const int bm = blockIdx.y * 128, bn = blockIdx.x * 64, bz = blockIdx.z;

    if (skipMode == 1) {
        if (bn > bm + 127) return;
    } else if (skipMode == 2) {
        bool band = (bm + 127 + bn + 63) >= (TT - 1);
        bool mem  = (bn == 0) && (bm <= NMTOK || bm + 127 >= TT - NMTOK + 1);
        if (!band && !mem) return;
    }
    int Keff = kLimitByRow ? min(K, bm + 128) : K;

    A += (size_t)bz * aBS;
    B += (size_t)bz * bBS;
    C += (size_t)bz * cBS;
    const float* ab = abias ? abias + (size_t)bz * abiasBS : nullptr;

    const int tid = threadIdx.x;
    const int lane = tid & 31, warp = tid >> 5;
    const int wm = warp & 3, wn = warp >> 2;
    const int g4 = lane >> 2, l4 = lane & 3;

    float acc[2][4][4] = {};
    float4 pa[4], pb[2];

    auto loadA = [&](int k0) {
        const int r = tid >> 3, k4 = (tid & 7) * 4;
        #pragma unroll
        for (int p = 0; p < 4; p++) {
            int row = bm + p * 32 + r;
            float4 v = make_float4(0.f, 0.f, 0.f, 0.f);
            if (row < M) v = *reinterpret_cast<const float4*>(A + (size_t)row * lda + k0 + k4);
            if (ab) {
                v.x += ab[k0 + k4 + 0];
                v.y += ab[k0 + k4 + 1];
                v.z += ab[k0 + k4 + 2];
                v.w += ab[k0 + k4 + 3];
            }
            pa[p] = v;
        }
    };
    auto loadB = [&](int k0) {
        if (TRANSB) {
            const int r = tid >> 3, k4 = (tid & 7) * 4;
            #pragma unroll
            for (int p = 0; p < 2; p++) {
                int row = bn + p * 32 + r;
                float4 v = make_float4(0.f, 0.f, 0.f, 0.f);
                if (row < N) v = *reinterpret_cast<const float4*>(B + (size_t)row * ldb + k0 + k4);
                pb[p] = v;
            }
        } else {
            const int r = tid >> 4, n4 = (tid & 15) * 4;
            #pragma unroll
            for (int p = 0; p < 2; p++) {
                int k = k0 + p * 16 + r;
                pb[p] = *reinterpret_cast<const float4*>(B + (size_t)k * ldb + bn + n4);
            }
        }
    };
    auto storeAB = [&]() {
        {
            const int r = tid >> 3, k4 = (tid & 7) * 4;
            #pragma unroll
            for (int p = 0; p < 4; p++)
                *reinterpret_cast<float4*>(&As[(p * 32 + r) * LDA_S + k4]) = pa[p];
        }
        if (TRANSB) {
            const int r = tid >> 3, k4 = (tid & 7) * 4;
            #pragma unroll
            for (int p = 0; p < 2; p++)
                *reinterpret_cast<float4*>(&Bs[(p * 32 + r) * LDB_NT + k4]) = pb[p];
        } else {
            const int r = tid >> 4, n4 = (tid & 15) * 4;
            #pragma unroll
            for (int p = 0; p < 2; p++)
                *reinterpret_cast<float4*>(&Bs[(p * 16 + r) * LDB_NN + n4]) = pb[p];
        }
    };

    loadA(0);
    loadB(0);

    for (int k0 = 0; k0 < Keff; k0 += 32) {
        storeAB();
        __syncthreads();
        if (k0 + 32 < Keff) { loadA(k0 + 32); loadB(k0 + 32); }

        #pragma unroll
        for (int ks = 0; ks < 4; ks++) {
            const int kk = ks * 8 + l4;
            uint32_t ah[2][4], al[2][4];
            #pragma unroll
            for (int am = 0; am < 2; am++) {
                int mb = wm * 32 + am * 16 + g4;
                float f0 = As[mb * LDA_S + kk];
                float f1 = As[(mb + 8) * LDA_S + kk];
                float f2 = As[mb * LDA_S + kk + 4];
                float f3 = As[(mb + 8) * LDA_S + kk + 4];
                split_tf32(f0, ah[am][0], al[am][0]);
                split_tf32(f1, ah[am][1], al[am][1]);
                split_tf32(f2, ah[am][2], al[am][2]);
                split_tf32(f3, ah[am][3], al[am][3]);
            }
            uint32_t bh[4][2], bl[4][2];
            #pragma unroll
            for (int an = 0; an < 4; an++) {
                int nb = wn * 32 + an * 8 + g4;
                float f0, f1;
                if (TRANSB) {
                    f0 = Bs[nb * LDB_NT + kk];
                    f1 = Bs[nb * LDB_NT + kk + 4];
                } else {
                    f0 = Bs[kk * LDB_NN + nb];
                    f1 = Bs[(kk + 4) * LDB_NN + nb];
                }
                split_tf32(f0, bh[an][0], bl[an][0]);
                split_tf32(f1, bh[an][1], bl[an][1]);
            }
            #pragma unroll
            for (int am = 0; am < 2; am++)
                #pragma unroll
                for (int an = 0; an < 4; an++) {
                    mma8(acc[am][an], ah[am], bh[an]);
                    mma8(acc[am][an], ah[am], bl[an]);
                    mma8(acc[am][an], al[am], bh[an]);
                }
        }
        __syncthreads();
    }

    #pragma unroll
    for (int am = 0; am < 2; am++) {
        int row0 = bm + wm * 32 + am * 16 + g4;
        #pragma unroll
        for (int an = 0; an < 4; an++) {
            int col0 = bn + wn * 32 + an * 8 + 2 * l4;
            float v0 = acc[am][an][0], v1 = acc[am][an][1];
            float v2 = acc[am][an][2], v3 = acc[am][an][3];
            if (cbias) {
                float b0 = cbias[col0], b1 = cbias[col0 + 1];
                v0 += b0; v1 += b1; v2 += b0; v3 += b1;
            }
            if (doRelu) {
                v0 = fmaxf(v0, 0.f); v1 = fmaxf(v1, 0.f);
                v2 = fmaxf(v2, 0.f); v3 = fmaxf(v3, 0.f);
            }
            if (row0 < M) {
                if (col0 < N)     C[(size_t)row0 * ldc + col0]     = v0;
                if (col0 + 1 < N) C[(size_t)row0 * ldc + col0 + 1] = v1;
            }
            if (row0 + 8 < M) {
                if (col0 < N)     C[(size_t)(row0 + 8) * ldc + col0]     = v2;
                if (col0 + 1 < N) C[(size_t)(row0 + 8) * ldc + col0 + 1] = v3;
            }
        }
    }
}

// ---------------- fused rel_shift + mask + scale + softmax ----------------
// One block per (h, i) row. Reads AC row (j <= jmax) and the two BD-raw
// segments, softmaxes in smem, writes P (with zeros out to the row's 128-block
// end so the K-limited PV GEMM reads exact zeros in the masked band).
__global__ __launch_bounds__(256)
void fused_softmax_kernel(float* __restrict__ P, const float* __restrict__ BD) {
    const int row = blockIdx.x;          // h*TT + i
    const int i = row % TT, h = row / TT;
    float* __restrict__ Pr = P + (size_t)row * TT;
    const float* __restrict__ BDh = BD + (size_t)h * TT * TT;

    const int jmax = (i < NMTOK) ? (NMTOK - 1)
                   : ((i >= TT - NMTOK) ? (TT - 1) : i);
    const int n = jmax + 1;

    __shared__ float s[TT];
    __shared__ float red[256];
    const int tid = threadIdx.x;

    float m = -1e38f;
    for (int j = tid; j < n; j += 256) {
        float bd;
        if (j <= i)          bd = BDh[(size_t)i * TT + (TT - 1 - i + j)];
        else if (j == i + 1) bd = 0.f;
        else                 bd = BDh[(size_t)(i + 1) * TT + (j - i - 2)];
        float v = (Pr[j] + bd) * 0.125f;
        s[j] = v;
        m = fmaxf(m, v);
    }
    red[tid] = m; __syncthreads();
    for (int st = 128; st > 0; st >>= 1) {
        if (tid < st) red[tid] = fmaxf(red[tid], red[tid + st]);
        __syncthreads();
    }
    m = red[0]; __syncthreads();

    float sum = 0.f;
    for (int j = tid; j < n; j += 256) {
        float e = expf(s[j] - m);
        s[j] = e;
        sum += e;
    }
    red[tid] = sum; __syncthreads();
    for (int st = 128; st > 0; st >>= 1) {
        if (tid < st) red[tid] += red[tid + st];
        __syncthreads();
    }
    const float inv = 1.f / red[0];

    const int zend = (i >= TT - NMTOK) ? TT : min(TT, ((i >> 7) + 1) << 7);
    for (int j = tid; j < zend; j += 256)
        Pr[j] = (j < n) ? s[j] * inv : 0.f;
}

// ---------------- residual add + layernorm ----------------
__global__ void add_ln_kernel(float* __restrict__ w, const float* __restrict__ delta,
                              const float* __restrict__ gam, const float* __restrict__ bta) {
    int row = blockIdx.x;
    int tid = threadIdx.x;
    __shared__ float red[256];
    float x0 = w[row * DM + tid]       + delta[row * DM + tid];
    float x1 = w[row * DM + tid + 256] + delta[row * DM + tid + 256];
    red[tid] = x0 + x1; __syncthreads();
    for (int s = 128; s > 0; s >>= 1) {
        if (tid < s) red[tid] += red[tid + s];
        __syncthreads();
    }
    float mean = red[0] * (1.f / DM);
    __syncthreads();
    float d0 = x0 - mean, d1 = x1 - mean;
    red[tid] = d0 * d0 + d1 * d1; __syncthreads();
    for (int s = 128; s > 0; s >>= 1) {
        if (tid < s) red[tid] += red[tid + s];
        __syncthreads();
    }
    float inv = 1.f / sqrtf(red[0] * (1.f / DM) + 1e-5f);
    w[row * DM + tid]       = d0 * inv * gam[tid]       + bta[tid];
    w[row * DM + tid + 256] = d1 * inv * gam[tid + 256] + bta[tid + 256];
}

__global__ void copy_out_kernel(float* __restrict__ out) {
    int idx = blockIdx.x * blockDim.x + threadIdx.x;
    if (idx < TT * DM) out[idx] = g_w[idx];
}

// ---------------- launcher ----------------
extern "C" void kernel_launch(void* const* d_in, const int* in_sizes, int n_in,
                              void* d_out, int out_size) {
    (void)in_sizes; (void)n_in; (void)out_size;
    const float* word_emb = (const float*)d_in[0];
    const float* mem_tok  = (const float*)d_in[1];
    const float* Wqkv     = (const float*)d_in[2];
    const float* Wr       = (const float*)d_in[3];
    const float* Wo       = (const float*)d_in[4];
    const float* ln1s     = (const float*)d_in[5];
    const float* ln1b     = (const float*)d_in[6];
    const float* W1       = (const float*)d_in[7];
    const float* b1       = (const float*)d_in[8];
    const float* W2       = (const float*)d_in[9];
    const float* b2       = (const float*)d_in[10];
    const float* ln2s     = (const float*)d_in[11];
    const float* ln2b     = (const float*)d_in[12];
    const float* rwb      = (const float*)d_in[13];
    const float* rrb      = (const float*)d_in[14];

    float *g_w_p, *g_pos_p, *g_hd_p, *g_r_p, *g_AC_p, *g_BD_p, *g_av_p, *g_tmp_p, *g_ff1_p;
    cudaGetSymbolAddress((void**)&g_w_p,   g_w);
    cudaGetSymbolAddress((void**)&g_pos_p, g_pos);
    cudaGetSymbolAddress((void**)&g_hd_p,  g_heads);
    cudaGetSymbolAddress((void**)&g_r_p,   g_r);
    cudaGetSymbolAddress((void**)&g_AC_p,  g_AC);
    cudaGetSymbolAddress((void**)&g_BD_p,  g_BD);
    cudaGetSymbolAddress((void**)&g_av_p,  g_av);
    cudaGetSymbolAddress((void**)&g_tmp_p, g_tmp);
    cudaGetSymbolAddress((void**)&g_ff1_p, g_ff1);

    const int TD = TT * DM;
    build_w_kernel<<<(TD + 255) / 256, 256>>>(word_emb, mem_tok);
    build_pos_kernel<<<(TD + 255) / 256, 256>>>();

    const int MB = (TT + 127) / 128;   // 17
    const int NB64 = (TT + 63) / 64;   // 33

    for (int l = 0; l < NLAY; l++) {
        mma_gemm<false><<<dim3(3 * DM / 64, MB, 1), 256>>>(
            g_w_p, DM, 0, nullptr, 0,
            Wqkv + (size_t)l * DM * 3 * DM, 3 * DM, 0,
            g_hd_p, 3 * DM, 0, nullptr, 0, TT, 3 * DM, DM, 0, 0);
        mma_gemm<false><<<dim3(DM / 64, MB, 1), 256>>>(
            g_pos_p, DM, 0, nullptr, 0,
            Wr + (size_t)l * DM * DM, DM, 0,
            g_r_p, DM, 0, nullptr, 0, TT, DM, DM, 0, 0);
        // AC (causal-lower tiles only)
        mma_gemm<true><<<dim3(NB64, MB, NH), 256>>>(
            g_hd_p, 3 * DM, DH, rwb, DH,
            g_hd_p + DM, 3 * DM, DH,
            g_AC_p, TT, (size_t)TT * TT, nullptr, 0, TT, TT, DH, 1, 0);
        // BD raw (anti-diagonal band + mem strips only)
        mma_gemm<true><<<dim3(NB64, MB, NH), 256>>>(
            g_hd_p, 3 * DM, DH, rrb, DH,
            g_r_p, DM, DH,
            g_BD_p, TT, (size_t)TT * TT, nullptr, 0, TT, TT, DH, 2, 0);
        // fused rel_shift + mask + scale + softmax (+ zero-fill to block edge)
        fused_softmax_kernel<<<NH * TT, 256>>>(g_AC_p, g_BD_p);
        // PV with per-block K limit (causal)
        mma_gemm<false><<<dim3(1, MB, NH), 256>>>(
            g_AC_p, TT, (size_t)TT * TT, nullptr, 0,
            g_hd_p + 2 * DM, 3 * DM, DH,
            g_av_p, DM, DH, nullptr, 0, TT, DH, TT, 0, 1);
        mma_gemm<false><<<dim3(DM / 64, MB, 1), 256>>>(
            g_av_p, DM, 0, nullptr, 0,
            Wo + (size_t)l * DM * DM, DM, 0,
            g_tmp_p, DM, 0, nullptr, 0, TT, DM, DM, 0, 0);
        add_ln_kernel<<<TT, 256>>>(g_w_p, g_tmp_p, ln1s + l * DM, ln1b + l * DM);
        mma_gemm<false><<<dim3(DI / 64, MB, 1), 256>>>(
            g_w_p, DM, 0, nullptr, 0,
            W1 + (size_t)l * DM * DI, DI, 0,
            g_ff1_p, DI, 0, b1 + (size_t)l * DI, 1, TT, DI, DM, 0, 0);
        mma_gemm<false><<<dim3(DM / 64, MB, 1), 256>>>(
            g_ff1_p, DI, 0, nullptr, 0,
            W2 + (size_t)l * DI * DM, DM, 0,
            g_tmp_p, DM, 0, b2 + (size_t)l * DM, 0, TT, DM, DI, 0, 0);
        add_ln_kernel<<<TT, 256>>>(g_w_p, g_tmp_p, ln2s + l * DM, ln2b + l * DM);
    }

    copy_out_kernel<<<(TD + 255) / 256, 256>>>((float*)d_out);
}